// round 2
// baseline (speedup 1.0000x reference)
#include <cuda_runtime.h>
#include <cstdint>

// FeatureICA: 8192 independent (G=4, D=256) AuxICA solves, 10 iterations.
// One warp per (b,t) position; x tile resident in registers; mask u = 1/(|y|+eps)
// via FMA-only Newton reciprocal (q-2 == -1 to ~1e-7); 4x4 solve via cofactors.

#define NPOS   8192
#define GRP    4
#define DD     256
#define DPL    8     // d-indices per lane (256 / 32)
#define NITER  10

__device__ __forceinline__ float fast_rcp(float x) {
    // x > 0 (x >= 1e-5 here). Bit-hack seed (~5% err) + 3 Newton steps -> ~1 ulp.
    float y = __int_as_float(0x7EF311C3 - __float_as_int(x));
    y = y * (2.0f - x * y);
    y = y * (2.0f - x * y);
    y = y * (2.0f - x * y);
    return y;
}

__device__ __forceinline__ float det3(
    float a00, float a01, float a02,
    float a10, float a11, float a12,
    float a20, float a21, float a22) {
    return a00 * (a11 * a22 - a12 * a21)
         - a01 * (a10 * a22 - a12 * a20)
         + a02 * (a10 * a21 - a11 * a20);
}

__device__ __forceinline__ void idx3(int k, int& r0, int& r1, int& r2) {
    r0 = (k == 0) ? 1 : 0;
    r1 = (k <= 1) ? 2 : 1;
    r2 = (k <= 2) ? 3 : 2;
}

// Cofactor C_{k,i} of 4x4 M (sign included).
__device__ __forceinline__ float cof(const float M[4][4], int k, int i) {
    int r0, r1, r2, c0, c1, c2;
    idx3(k, r0, r1, r2);
    idx3(i, c0, c1, c2);
    float d = det3(M[r0][c0], M[r0][c1], M[r0][c2],
                   M[r1][c0], M[r1][c1], M[r1][c2],
                   M[r2][c0], M[r2][c1], M[r2][c2]);
    return (((k + i) & 1) ? -d : d);
}

__global__ void __launch_bounds__(256)
ica_kernel(const float* __restrict__ x, float* __restrict__ out) {
    const int lane = threadIdx.x & 31;
    const int wpos = blockIdx.x * (blockDim.x >> 5) + (threadIdx.x >> 5);
    if (wpos >= NPOS) return;

    const float* xp = x + (size_t)wpos * (GRP * DD);

    // Load this position's 4x256 tile; lane owns d = j*32 + lane (coalesced).
    float xg[GRP][DPL];
    #pragma unroll
    for (int g = 0; g < GRP; g++)
        #pragma unroll
        for (int j = 0; j < DPL; j++)
            xg[g][j] = xp[g * DD + j * 32 + lane];

    float W[4][4] = {{1.f,0.f,0.f,0.f},{0.f,1.f,0.f,0.f},
                     {0.f,0.f,1.f,0.f},{0.f,0.f,0.f,1.f}};

    const float eps    = 1e-5f;
    const float mfloor = 1e-5f;
    const float invD   = 1.0f / 256.0f;

    #pragma unroll 1
    for (int it = 0; it < NITER; it++) {
        #pragma unroll
        for (int k = 0; k < GRP; k++) {
            // u_k from current W row k (row k is untouched until this step,
            // so it equals the start-of-iteration W -- matches reference).
            float u[DPL];
            #pragma unroll
            for (int j = 0; j < DPL; j++) {
                float y = W[k][0] * xg[0][j];
                y = fmaf(W[k][1], xg[1][j], y);
                y = fmaf(W[k][2], xg[2][j], y);
                y = fmaf(W[k][3], xg[3][j], y);
                float r = fabsf(y) + eps;
                u[j] = fmaxf(fast_rcp(r), mfloor);
            }

            // Partial weighted Gram (10 unique entries, symmetric).
            float p00=0.f,p01=0.f,p02=0.f,p03=0.f,p11=0.f,
                  p12=0.f,p13=0.f,p22=0.f,p23=0.f,p33=0.f;
            #pragma unroll
            for (int j = 0; j < DPL; j++) {
                float t0 = u[j] * xg[0][j];
                float t1 = u[j] * xg[1][j];
                float t2 = u[j] * xg[2][j];
                float t3 = u[j] * xg[3][j];
                p00 = fmaf(t0, xg[0][j], p00);
                p01 = fmaf(t0, xg[1][j], p01);
                p02 = fmaf(t0, xg[2][j], p02);
                p03 = fmaf(t0, xg[3][j], p03);
                p11 = fmaf(t1, xg[1][j], p11);
                p12 = fmaf(t1, xg[2][j], p12);
                p13 = fmaf(t1, xg[3][j], p13);
                p22 = fmaf(t2, xg[2][j], p22);
                p23 = fmaf(t2, xg[3][j], p23);
                p33 = fmaf(t3, xg[3][j], p33);
            }

            // Butterfly reduce -> every lane holds the full sums.
            #pragma unroll
            for (int off = 16; off > 0; off >>= 1) {
                p00 += __shfl_xor_sync(0xffffffffu, p00, off);
                p01 += __shfl_xor_sync(0xffffffffu, p01, off);
                p02 += __shfl_xor_sync(0xffffffffu, p02, off);
                p03 += __shfl_xor_sync(0xffffffffu, p03, off);
                p11 += __shfl_xor_sync(0xffffffffu, p11, off);
                p12 += __shfl_xor_sync(0xffffffffu, p12, off);
                p13 += __shfl_xor_sync(0xffffffffu, p13, off);
                p22 += __shfl_xor_sync(0xffffffffu, p22, off);
                p23 += __shfl_xor_sync(0xffffffffu, p23, off);
                p33 += __shfl_xor_sync(0xffffffffu, p33, off);
            }

            float V[4][4];
            V[0][0] = p00 * invD;
            V[0][1] = V[1][0] = p01 * invD;
            V[0][2] = V[2][0] = p02 * invD;
            V[0][3] = V[3][0] = p03 * invD;
            V[1][1] = p11 * invD;
            V[1][2] = V[2][1] = p12 * invD;
            V[1][3] = V[3][1] = p13 * invD;
            V[2][2] = p22 * invD;
            V[2][3] = V[3][2] = p23 * invD;
            V[3][3] = p33 * invD;

            // M = W @ V (current, partially-updated W -- matches reference).
            float M[4][4];
            #pragma unroll
            for (int r = 0; r < 4; r++)
                #pragma unroll
                for (int c = 0; c < 4; c++) {
                    float s = W[r][0] * V[0][c];
                    s = fmaf(W[r][1], V[1][c], s);
                    s = fmaf(W[r][2], V[2][c], s);
                    s = fmaf(W[r][3], V[3][c], s);
                    M[r][c] = s;
                }

            // Solve M w = e_k via row-k cofactors (w_i = C_{k,i} / det).
            float c0 = cof(M, k, 0);
            float c1 = cof(M, k, 1);
            float c2 = cof(M, k, 2);
            float c3 = cof(M, k, 3);
            float det = M[k][0]*c0 + M[k][1]*c1 + M[k][2]*c2 + M[k][3]*c3;
            float idet = 1.0f / det;
            float w0 = c0 * idet, w1 = c1 * idet, w2 = c2 * idet, w3 = c3 * idet;

            // Normalize: w /= (sqrt(w^T V w) + eps)
            float t0 = V[0][0]*w0 + V[0][1]*w1 + V[0][2]*w2 + V[0][3]*w3;
            float t1 = V[1][0]*w0 + V[1][1]*w1 + V[1][2]*w2 + V[1][3]*w3;
            float t2 = V[2][0]*w0 + V[2][1]*w1 + V[2][2]*w2 + V[2][3]*w3;
            float t3 = V[3][0]*w0 + V[3][1]*w1 + V[3][2]*w2 + V[3][3]*w3;
            float s  = w0*t0 + w1*t1 + w2*t2 + w3*t3;
            float inv = 1.0f / (sqrtf(s) + eps);
            W[k][0] = w0 * inv;
            W[k][1] = w1 * inv;
            W[k][2] = w2 * inv;
            W[k][3] = w3 * inv;
        }
    }

    // scale_g = diag(inv(W))_g = C_{g,g}(W) / det(W)
    float d0 = cof(W, 0, 0);
    float d1 = cof(W, 0, 1);
    float d2 = cof(W, 0, 2);
    float d3 = cof(W, 0, 3);
    float detW = W[0][0]*d0 + W[0][1]*d1 + W[0][2]*d2 + W[0][3]*d3;
    float idetW = 1.0f / detW;
    float scale[4];
    scale[0] = d0 * idetW;
    scale[1] = cof(W, 1, 1) * idetW;
    scale[2] = cof(W, 2, 2) * idetW;
    scale[3] = cof(W, 3, 3) * idetW;

    float* op = out + (size_t)wpos * (GRP * DD);
    #pragma unroll
    for (int g = 0; g < GRP; g++) {
        #pragma unroll
        for (int j = 0; j < DPL; j++) {
            float y = W[g][0] * xg[0][j];
            y = fmaf(W[g][1], xg[1][j], y);
            y = fmaf(W[g][2], xg[2][j], y);
            y = fmaf(W[g][3], xg[3][j], y);
            op[g * DD + j * 32 + lane] = y * scale[g];
        }
    }
}

extern "C" void kernel_launch(void* const* d_in, const int* in_sizes, int n_in,
                              void* d_out, int out_size) {
    const float* x = (const float*)d_in[0];
    float* out = (float*)d_out;
    (void)in_sizes; (void)n_in; (void)out_size;
    // 8192 positions, 1 warp each; 8 warps per block.
    ica_kernel<<<NPOS / 8, 256>>>(x, out);
}

// round 3
// speedup vs baseline: 1.0297x; 1.0297x over previous
#include <cuda_runtime.h>
#include <cstdint>

// FeatureICA: 8192 independent (G=4, D=256) AuxICA solves, 10 iterations.
// One warp per (b,t) position; x tile resident in packed f32x2 registers.
// Mask u = 1/(|y|+eps) (q-2 == -1 to ~1e-11) via MUFU rcp.approx, with the
// 1/D Gram normalization folded into the mask scale. 4x4 solve via cofactors.

#define NPOS   8192
#define GRP    4
#define DD     256
#define DPL    8     // d-indices per lane (256 / 32)
#define NPAIR  4     // f32x2 pairs per lane
#define NITER  10

typedef unsigned long long u64;

__device__ __forceinline__ u64 pk2(float lo, float hi) {
    u64 r; asm("mov.b64 %0, {%1, %2};" : "=l"(r) : "f"(lo), "f"(hi)); return r;
}
__device__ __forceinline__ void upk2(u64 v, float& lo, float& hi) {
    asm("mov.b64 {%0, %1}, %2;" : "=f"(lo), "=f"(hi) : "l"(v));
}
__device__ __forceinline__ u64 fma2(u64 a, u64 b, u64 c) {
    u64 r; asm("fma.rn.f32x2 %0, %1, %2, %3;" : "=l"(r) : "l"(a), "l"(b), "l"(c)); return r;
}
__device__ __forceinline__ u64 mul2(u64 a, u64 b) {
    u64 r; asm("mul.rn.f32x2 %0, %1, %2;" : "=l"(r) : "l"(a), "l"(b)); return r;
}
__device__ __forceinline__ float frcp(float x) {
    float r; asm("rcp.approx.f32 %0, %1;" : "=f"(r) : "f"(x)); return r;
}
__device__ __forceinline__ float fsqrt_ap(float x) {
    float r; asm("sqrt.approx.f32 %0, %1;" : "=f"(r) : "f"(x)); return r;
}

__device__ __forceinline__ float det3(
    float a00, float a01, float a02,
    float a10, float a11, float a12,
    float a20, float a21, float a22) {
    return a00 * (a11 * a22 - a12 * a21)
         - a01 * (a10 * a22 - a12 * a20)
         + a02 * (a10 * a21 - a11 * a20);
}

__device__ __forceinline__ void idx3(int k, int& r0, int& r1, int& r2) {
    r0 = (k == 0) ? 1 : 0;
    r1 = (k <= 1) ? 2 : 1;
    r2 = (k <= 2) ? 3 : 2;
}

// Cofactor C_{k,i} of 4x4 M (sign included).
__device__ __forceinline__ float cof(const float M[4][4], int k, int i) {
    int r0, r1, r2, c0, c1, c2;
    idx3(k, r0, r1, r2);
    idx3(i, c0, c1, c2);
    float d = det3(M[r0][c0], M[r0][c1], M[r0][c2],
                   M[r1][c0], M[r1][c1], M[r1][c2],
                   M[r2][c0], M[r2][c1], M[r2][c2]);
    return (((k + i) & 1) ? -d : d);
}

__global__ void __launch_bounds__(256)
ica_kernel(const float* __restrict__ x, float* __restrict__ out) {
    const int lane = threadIdx.x & 31;
    const int wpos = blockIdx.x * (blockDim.x >> 5) + (threadIdx.x >> 5);
    if (wpos >= NPOS) return;

    const float* xp = x + (size_t)wpos * (GRP * DD);

    // Load 4x256 tile; lane owns d = j*32 + lane (coalesced). Pack j-pairs.
    u64 xg[GRP][NPAIR];
    #pragma unroll
    for (int g = 0; g < GRP; g++) {
        #pragma unroll
        for (int p = 0; p < NPAIR; p++) {
            float lo = xp[g * DD + (2 * p)     * 32 + lane];
            float hi = xp[g * DD + (2 * p + 1) * 32 + lane];
            xg[g][p] = pk2(lo, hi);
        }
    }

    float W[4][4] = {{1.f,0.f,0.f,0.f},{0.f,1.f,0.f,0.f},
                     {0.f,0.f,1.f,0.f},{0.f,0.f,0.f,1.f}};

    const float eps     = 1e-5f;
    // mask scaled by 1/D=1/256: u' = rcp(256*|y| + 256*eps), floor 1e-5/256.
    const float RSCALE  = 256.0f;
    const float RBIAS   = 256.0f * 1e-5f;
    const float UFLOOR  = 1e-5f / 256.0f;

    #pragma unroll 1
    for (int it = 0; it < NITER; it++) {
        #pragma unroll
        for (int k = 0; k < GRP; k++) {
            // Broadcast-pack W row k for packed y compute.
            u64 wb0 = pk2(W[k][0], W[k][0]);
            u64 wb1 = pk2(W[k][1], W[k][1]);
            u64 wb2 = pk2(W[k][2], W[k][2]);
            u64 wb3 = pk2(W[k][3], W[k][3]);

            // Mask u'_k (already divided by D), packed.
            u64 u2[NPAIR];
            #pragma unroll
            for (int p = 0; p < NPAIR; p++) {
                u64 y2 = mul2(wb0, xg[0][p]);
                y2 = fma2(wb1, xg[1][p], y2);
                y2 = fma2(wb2, xg[2][p], y2);
                y2 = fma2(wb3, xg[3][p], y2);
                float y0, y1;
                upk2(y2, y0, y1);
                float r0 = fmaf(fabsf(y0), RSCALE, RBIAS);
                float r1 = fmaf(fabsf(y1), RSCALE, RBIAS);
                float u0 = fmaxf(frcp(r0), UFLOOR);
                float u1 = fmaxf(frcp(r1), UFLOOR);
                u2[p] = pk2(u0, u1);
            }

            // Weighted Gram (10 unique symmetric entries), packed accumulate.
            u64 p00=0,p01=0,p02=0,p03=0,p11=0,p12=0,p13=0,p22=0,p23=0,p33=0;
            #pragma unroll
            for (int p = 0; p < NPAIR; p++) {
                u64 t0 = mul2(u2[p], xg[0][p]);
                u64 t1 = mul2(u2[p], xg[1][p]);
                u64 t2 = mul2(u2[p], xg[2][p]);
                u64 t3 = mul2(u2[p], xg[3][p]);
                p00 = fma2(t0, xg[0][p], p00);
                p01 = fma2(t0, xg[1][p], p01);
                p02 = fma2(t0, xg[2][p], p02);
                p03 = fma2(t0, xg[3][p], p03);
                p11 = fma2(t1, xg[1][p], p11);
                p12 = fma2(t1, xg[2][p], p12);
                p13 = fma2(t1, xg[3][p], p13);
                p22 = fma2(t2, xg[2][p], p22);
                p23 = fma2(t2, xg[3][p], p23);
                p33 = fma2(t3, xg[3][p], p33);
            }

            // Horizontal add (packed -> scalar), then butterfly reduce.
            float s00, s01, s02, s03, s11, s12, s13, s22, s23, s33, ha, hb;
            upk2(p00, ha, hb); s00 = ha + hb;
            upk2(p01, ha, hb); s01 = ha + hb;
            upk2(p02, ha, hb); s02 = ha + hb;
            upk2(p03, ha, hb); s03 = ha + hb;
            upk2(p11, ha, hb); s11 = ha + hb;
            upk2(p12, ha, hb); s12 = ha + hb;
            upk2(p13, ha, hb); s13 = ha + hb;
            upk2(p22, ha, hb); s22 = ha + hb;
            upk2(p23, ha, hb); s23 = ha + hb;
            upk2(p33, ha, hb); s33 = ha + hb;

            #pragma unroll
            for (int off = 16; off > 0; off >>= 1) {
                s00 += __shfl_xor_sync(0xffffffffu, s00, off);
                s01 += __shfl_xor_sync(0xffffffffu, s01, off);
                s02 += __shfl_xor_sync(0xffffffffu, s02, off);
                s03 += __shfl_xor_sync(0xffffffffu, s03, off);
                s11 += __shfl_xor_sync(0xffffffffu, s11, off);
                s12 += __shfl_xor_sync(0xffffffffu, s12, off);
                s13 += __shfl_xor_sync(0xffffffffu, s13, off);
                s22 += __shfl_xor_sync(0xffffffffu, s22, off);
                s23 += __shfl_xor_sync(0xffffffffu, s23, off);
                s33 += __shfl_xor_sync(0xffffffffu, s33, off);
            }

            // V already includes the 1/D factor (folded into the mask).
            float V[4][4];
            V[0][0] = s00;
            V[0][1] = V[1][0] = s01;
            V[0][2] = V[2][0] = s02;
            V[0][3] = V[3][0] = s03;
            V[1][1] = s11;
            V[1][2] = V[2][1] = s12;
            V[1][3] = V[3][1] = s13;
            V[2][2] = s22;
            V[2][3] = V[3][2] = s23;
            V[3][3] = s33;

            // M = W @ V (current, partially-updated W -- matches reference).
            float M[4][4];
            #pragma unroll
            for (int r = 0; r < 4; r++)
                #pragma unroll
                for (int c = 0; c < 4; c++) {
                    float s = W[r][0] * V[0][c];
                    s = fmaf(W[r][1], V[1][c], s);
                    s = fmaf(W[r][2], V[2][c], s);
                    s = fmaf(W[r][3], V[3][c], s);
                    M[r][c] = s;
                }

            // Solve M w = e_k via row-k cofactors (w_i = C_{k,i} / det).
            float c0 = cof(M, k, 0);
            float c1 = cof(M, k, 1);
            float c2 = cof(M, k, 2);
            float c3 = cof(M, k, 3);
            float det = M[k][0]*c0 + M[k][1]*c1 + M[k][2]*c2 + M[k][3]*c3;
            float idet = frcp(det);
            float w0 = c0 * idet, w1 = c1 * idet, w2 = c2 * idet, w3 = c3 * idet;

            // Normalize: w /= (sqrt(w^T V w) + eps)
            float t0 = V[0][0]*w0 + V[0][1]*w1 + V[0][2]*w2 + V[0][3]*w3;
            float t1 = V[1][0]*w0 + V[1][1]*w1 + V[1][2]*w2 + V[1][3]*w3;
            float t2 = V[2][0]*w0 + V[2][1]*w1 + V[2][2]*w2 + V[2][3]*w3;
            float t3 = V[3][0]*w0 + V[3][1]*w1 + V[3][2]*w2 + V[3][3]*w3;
            float s  = w0*t0 + w1*t1 + w2*t2 + w3*t3;
            float inv = frcp(fsqrt_ap(s) + eps);
            W[k][0] = w0 * inv;
            W[k][1] = w1 * inv;
            W[k][2] = w2 * inv;
            W[k][3] = w3 * inv;
        }
    }

    // scale_g = diag(inv(W))_g = C_{g,g}(W) / det(W)
    float d0 = cof(W, 0, 0);
    float d1 = cof(W, 0, 1);
    float d2 = cof(W, 0, 2);
    float d3 = cof(W, 0, 3);
    float detW = W[0][0]*d0 + W[0][1]*d1 + W[0][2]*d2 + W[0][3]*d3;
    float idetW = frcp(detW);
    float scale[4];
    scale[0] = d0 * idetW;
    scale[1] = cof(W, 1, 1) * idetW;
    scale[2] = cof(W, 2, 2) * idetW;
    scale[3] = cof(W, 3, 3) * idetW;

    float* op = out + (size_t)wpos * (GRP * DD);
    #pragma unroll
    for (int g = 0; g < GRP; g++) {
        u64 wb0 = pk2(W[g][0], W[g][0]);
        u64 wb1 = pk2(W[g][1], W[g][1]);
        u64 wb2 = pk2(W[g][2], W[g][2]);
        u64 wb3 = pk2(W[g][3], W[g][3]);
        u64 sc  = pk2(scale[g], scale[g]);
        #pragma unroll
        for (int p = 0; p < NPAIR; p++) {
            u64 y2 = mul2(wb0, xg[0][p]);
            y2 = fma2(wb1, xg[1][p], y2);
            y2 = fma2(wb2, xg[2][p], y2);
            y2 = fma2(wb3, xg[3][p], y2);
            y2 = mul2(y2, sc);
            float y0, y1;
            upk2(y2, y0, y1);
            op[g * DD + (2 * p)     * 32 + lane] = y0;
            op[g * DD + (2 * p + 1) * 32 + lane] = y1;
        }
    }
}

extern "C" void kernel_launch(void* const* d_in, const int* in_sizes, int n_in,
                              void* d_out, int out_size) {
    const float* x = (const float*)d_in[0];
    float* out = (float*)d_out;
    (void)in_sizes; (void)n_in; (void)out_size;
    // 8192 positions, 1 warp each; 8 warps per block.
    ica_kernel<<<NPOS / 8, 256>>>(x, out);
}

// round 6
// speedup vs baseline: 1.3467x; 1.3079x over previous
#include <cuda_runtime.h>
#include <cstdint>

// FeatureICA: 8192 independent (G=4, D=256) AuxICA solves, 10 iterations.
// TWO positions per warp (16 lanes each, 16 contiguous d-elems/lane, so f32x2
// pairs load/store as LDG.128/STG.128 with zero packing MOVs). Mask+Gram fused.
// Mask u = 1/(|y|+eps) via MUFU rcp.approx with 1/D folded in. 4x4 via cofactors.
// Warp-uniform 4x4 algebra + 4-level butterfly serve 2 positions per warp.

#define NPOS   8192
#define GRP    4
#define DD     256
#define NPAIR  8     // f32x2 pairs per lane (16 floats, contiguous)
#define NITER  10

typedef unsigned long long u64;

__device__ __forceinline__ u64 pk2(float lo, float hi) {
    u64 r; asm("mov.b64 %0, {%1, %2};" : "=l"(r) : "f"(lo), "f"(hi)); return r;
}
__device__ __forceinline__ void upk2(u64 v, float& lo, float& hi) {
    asm("mov.b64 {%0, %1}, %2;" : "=f"(lo), "=f"(hi) : "l"(v));
}
__device__ __forceinline__ u64 fma2(u64 a, u64 b, u64 c) {
    u64 r; asm("fma.rn.f32x2 %0, %1, %2, %3;" : "=l"(r) : "l"(a), "l"(b), "l"(c)); return r;
}
__device__ __forceinline__ u64 mul2(u64 a, u64 b) {
    u64 r; asm("mul.rn.f32x2 %0, %1, %2;" : "=l"(r) : "l"(a), "l"(b)); return r;
}
__device__ __forceinline__ float frcp(float x) {
    float r; asm("rcp.approx.f32 %0, %1;" : "=f"(r) : "f"(x)); return r;
}
__device__ __forceinline__ float fsqrt_ap(float x) {
    float r; asm("sqrt.approx.f32 %0, %1;" : "=f"(r) : "f"(x)); return r;
}

__device__ __forceinline__ float det3(
    float a00, float a01, float a02,
    float a10, float a11, float a12,
    float a20, float a21, float a22) {
    return a00 * (a11 * a22 - a12 * a21)
         - a01 * (a10 * a22 - a12 * a20)
         + a02 * (a10 * a21 - a11 * a20);
}

__device__ __forceinline__ void idx3(int k, int& r0, int& r1, int& r2) {
    r0 = (k == 0) ? 1 : 0;
    r1 = (k <= 1) ? 2 : 1;
    r2 = (k <= 2) ? 3 : 2;
}

// Cofactor C_{k,i} of 4x4 M (sign included). k,i are compile-time consts
// (k-loop fully unrolled) so M stays in registers.
__device__ __forceinline__ float cof(const float M[4][4], int k, int i) {
    int r0, r1, r2, c0, c1, c2;
    idx3(k, r0, r1, r2);
    idx3(i, c0, c1, c2);
    float d = det3(M[r0][c0], M[r0][c1], M[r0][c2],
                   M[r1][c0], M[r1][c1], M[r1][c2],
                   M[r2][c0], M[r2][c1], M[r2][c2]);
    return (((k + i) & 1) ? -d : d);
}

__global__ void __launch_bounds__(128)
ica_kernel(const float* __restrict__ x, float* __restrict__ out) {
    const int lane = threadIdx.x & 31;
    const int half = lane >> 4;          // which position within the warp
    const int l16  = lane & 15;          // lane within the 16-lane half
    const int wid  = blockIdx.x * (blockDim.x >> 5) + (threadIdx.x >> 5);
    const int pos  = wid * 2 + half;

    // Lane owns contiguous d = l16*16 .. l16*16+15 of each group row.
    const float* xp = x + (size_t)pos * (GRP * DD) + l16 * 16;

    // Load 4 groups x 8 f32x2 pairs via LDG.128 (pairs are memory-adjacent,
    // so each u64 is already {f[d], f[d+1]} -- no packing instructions).
    u64 xg[GRP][NPAIR];
    #pragma unroll
    for (int g = 0; g < GRP; g++) {
        const ulonglong2* xv = (const ulonglong2*)(xp + g * DD);
        #pragma unroll
        for (int q = 0; q < 4; q++) {
            ulonglong2 v = xv[q];
            xg[g][2 * q]     = v.x;
            xg[g][2 * q + 1] = v.y;
        }
    }

    float W[4][4] = {{1.f,0.f,0.f,0.f},{0.f,1.f,0.f,0.f},
                     {0.f,0.f,1.f,0.f},{0.f,0.f,0.f,1.f}};

    const float eps    = 1e-5f;
    // mask scaled by 1/D=1/256: u' = rcp(256*|y| + 256*eps), floor 1e-5/256.
    const float RSCALE = 256.0f;
    const float RBIAS  = 256.0f * 1e-5f;
    const float UFLOOR = 1e-5f / 256.0f;

    #pragma unroll 1
    for (int it = 0; it < NITER; it++) {
        #pragma unroll
        for (int k = 0; k < GRP; k++) {
            // Broadcast-pack current W row k (per-half, already correct).
            u64 wb0 = pk2(W[k][0], W[k][0]);
            u64 wb1 = pk2(W[k][1], W[k][1]);
            u64 wb2 = pk2(W[k][2], W[k][2]);
            u64 wb3 = pk2(W[k][3], W[k][3]);

            // Fused mask + weighted-Gram accumulation (10 symmetric entries).
            u64 p00=0,p01=0,p02=0,p03=0,p11=0,p12=0,p13=0,p22=0,p23=0,p33=0;
            #pragma unroll
            for (int p = 0; p < NPAIR; p++) {
                u64 y2 = mul2(wb0, xg[0][p]);
                y2 = fma2(wb1, xg[1][p], y2);
                y2 = fma2(wb2, xg[2][p], y2);
                y2 = fma2(wb3, xg[3][p], y2);
                float y0, y1;
                upk2(y2, y0, y1);
                float r0 = fmaf(fabsf(y0), RSCALE, RBIAS);
                float r1 = fmaf(fabsf(y1), RSCALE, RBIAS);
                float u0 = fmaxf(frcp(r0), UFLOOR);
                float u1 = fmaxf(frcp(r1), UFLOOR);
                u64 uu = pk2(u0, u1);

                u64 t0 = mul2(uu, xg[0][p]);
                u64 t1 = mul2(uu, xg[1][p]);
                u64 t2 = mul2(uu, xg[2][p]);
                u64 t3 = mul2(uu, xg[3][p]);
                p00 = fma2(t0, xg[0][p], p00);
                p01 = fma2(t0, xg[1][p], p01);
                p02 = fma2(t0, xg[2][p], p02);
                p03 = fma2(t0, xg[3][p], p03);
                p11 = fma2(t1, xg[1][p], p11);
                p12 = fma2(t1, xg[2][p], p12);
                p13 = fma2(t1, xg[3][p], p13);
                p22 = fma2(t2, xg[2][p], p22);
                p23 = fma2(t2, xg[3][p], p23);
                p33 = fma2(t3, xg[3][p], p33);
            }

            // Horizontal add (packed -> scalar).
            float s00, s01, s02, s03, s11, s12, s13, s22, s23, s33, ha, hb;
            upk2(p00, ha, hb); s00 = ha + hb;
            upk2(p01, ha, hb); s01 = ha + hb;
            upk2(p02, ha, hb); s02 = ha + hb;
            upk2(p03, ha, hb); s03 = ha + hb;
            upk2(p11, ha, hb); s11 = ha + hb;
            upk2(p12, ha, hb); s12 = ha + hb;
            upk2(p13, ha, hb); s13 = ha + hb;
            upk2(p22, ha, hb); s22 = ha + hb;
            upk2(p23, ha, hb); s23 = ha + hb;
            upk2(p33, ha, hb); s33 = ha + hb;

            // 4-level butterfly: offsets 1,2,4,8 stay inside each 16-lane half.
            #pragma unroll
            for (int off = 8; off > 0; off >>= 1) {
                s00 += __shfl_xor_sync(0xffffffffu, s00, off);
                s01 += __shfl_xor_sync(0xffffffffu, s01, off);
                s02 += __shfl_xor_sync(0xffffffffu, s02, off);
                s03 += __shfl_xor_sync(0xffffffffu, s03, off);
                s11 += __shfl_xor_sync(0xffffffffu, s11, off);
                s12 += __shfl_xor_sync(0xffffffffu, s12, off);
                s13 += __shfl_xor_sync(0xffffffffu, s13, off);
                s22 += __shfl_xor_sync(0xffffffffu, s22, off);
                s23 += __shfl_xor_sync(0xffffffffu, s23, off);
                s33 += __shfl_xor_sync(0xffffffffu, s33, off);
            }

            // V already includes the 1/D factor (folded into the mask).
            float V[4][4];
            V[0][0] = s00;
            V[0][1] = V[1][0] = s01;
            V[0][2] = V[2][0] = s02;
            V[0][3] = V[3][0] = s03;
            V[1][1] = s11;
            V[1][2] = V[2][1] = s12;
            V[1][3] = V[3][1] = s13;
            V[2][2] = s22;
            V[2][3] = V[3][2] = s23;
            V[3][3] = s33;

            // M = W @ V (current, partially-updated W -- matches reference).
            float M[4][4];
            #pragma unroll
            for (int r = 0; r < 4; r++)
                #pragma unroll
                for (int c = 0; c < 4; c++) {
                    float s = W[r][0] * V[0][c];
                    s = fmaf(W[r][1], V[1][c], s);
                    s = fmaf(W[r][2], V[2][c], s);
                    s = fmaf(W[r][3], V[3][c], s);
                    M[r][c] = s;
                }

            // Solve M w = e_k via row-k cofactors (w_i = C_{k,i} / det).
            float c0 = cof(M, k, 0);
            float c1 = cof(M, k, 1);
            float c2 = cof(M, k, 2);
            float c3 = cof(M, k, 3);
            float det = M[k][0]*c0 + M[k][1]*c1 + M[k][2]*c2 + M[k][3]*c3;
            float idet = frcp(det);
            float w0 = c0 * idet, w1 = c1 * idet, w2 = c2 * idet, w3 = c3 * idet;

            // Normalize: w /= (sqrt(w^T V w) + eps)
            float t0 = V[0][0]*w0 + V[0][1]*w1 + V[0][2]*w2 + V[0][3]*w3;
            float t1 = V[1][0]*w0 + V[1][1]*w1 + V[1][2]*w2 + V[1][3]*w3;
            float t2 = V[2][0]*w0 + V[2][1]*w1 + V[2][2]*w2 + V[2][3]*w3;
            float t3 = V[3][0]*w0 + V[3][1]*w1 + V[3][2]*w2 + V[3][3]*w3;
            float s  = w0*t0 + w1*t1 + w2*t2 + w3*t3;
            float inv = frcp(fsqrt_ap(s) + eps);
            W[k][0] = w0 * inv;
            W[k][1] = w1 * inv;
            W[k][2] = w2 * inv;
            W[k][3] = w3 * inv;
        }
    }

    // scale_g = diag(inv(W))_g = C_{g,g}(W) / det(W)
    float d0 = cof(W, 0, 0);
    float d1 = cof(W, 0, 1);
    float d2 = cof(W, 0, 2);
    float d3 = cof(W, 0, 3);
    float detW = W[0][0]*d0 + W[0][1]*d1 + W[0][2]*d2 + W[0][3]*d3;
    float idetW = frcp(detW);
    float scale[4];
    scale[0] = d0 * idetW;
    scale[1] = cof(W, 1, 1) * idetW;
    scale[2] = cof(W, 2, 2) * idetW;
    scale[3] = cof(W, 3, 3) * idetW;

    float* op = out + (size_t)pos * (GRP * DD) + l16 * 16;
    #pragma unroll
    for (int g = 0; g < GRP; g++) {
        u64 wb0 = pk2(W[g][0], W[g][0]);
        u64 wb1 = pk2(W[g][1], W[g][1]);
        u64 wb2 = pk2(W[g][2], W[g][2]);
        u64 wb3 = pk2(W[g][3], W[g][3]);
        u64 sc  = pk2(scale[g], scale[g]);
        ulonglong2* ov = (ulonglong2*)(op + g * DD);
        #pragma unroll
        for (int q = 0; q < 4; q++) {
            u64 ya = mul2(wb0, xg[0][2 * q]);
            ya = fma2(wb1, xg[1][2 * q], ya);
            ya = fma2(wb2, xg[2][2 * q], ya);
            ya = fma2(wb3, xg[3][2 * q], ya);
            ya = mul2(ya, sc);
            u64 yb = mul2(wb0, xg[0][2 * q + 1]);
            yb = fma2(wb1, xg[1][2 * q + 1], yb);
            yb = fma2(wb2, xg[2][2 * q + 1], yb);
            yb = fma2(wb3, xg[3][2 * q + 1], yb);
            yb = mul2(yb, sc);
            ulonglong2 v; v.x = ya; v.y = yb;
            ov[q] = v;
        }
    }
}

extern "C" void kernel_launch(void* const* d_in, const int* in_sizes, int n_in,
                              void* d_out, int out_size) {
    const float* x = (const float*)d_in[0];
    float* out = (float*)d_out;
    (void)in_sizes; (void)n_in; (void)out_size;
    // 8192 positions, 2 per warp, 4 warps per 128-thread block -> 1024 blocks.
    ica_kernel<<<NPOS / 8, 128>>>(x, out);
}

// round 10
// speedup vs baseline: 1.4388x; 1.0684x over previous
#include <cuda_runtime.h>
#include <cstdint>

// FeatureICA: 8192 independent (G=4, D=256) AuxICA solves, 10 iterations.
// Two positions per warp (16 lanes each). The 4x256 x-tile lives in shared
// memory (lane-interleaved u64 layout, conflict-free LDS.64) so registers
// drop ~128 -> ~75 and occupancy becomes smem-limited (28 warps/SM) instead
// of register-limited (16). Mask+Gram fused; mask u = 1/(|y|+eps) via MUFU
// rcp with the 1/D Gram factor folded in (mask floor dropped: would need
// |y| > 1e5, unreachable since normalization pins E|y| ~ 1). 4x4 solve via
// row-k cofactors; normalization uses the scale-invariance of
// w/(sqrt(w'Vw)+eps) to absorb the 1/det (sign restored via copysign).
// Output scale diag(inv(W)) is premultiplied into the W rows for the store.

#define NPOS   8192
#define GRP    4
#define DD     256
#define NPAIR  8          // u64 (f32x2) pairs per lane per group
#define NITER  10
#define WPB    4          // warps per block
#define HPB    (2 * WPB)  // positions (halves) per block

typedef unsigned long long u64;

__device__ __forceinline__ u64 pk2(float lo, float hi) {
    u64 r; asm("mov.b64 %0, {%1, %2};" : "=l"(r) : "f"(lo), "f"(hi)); return r;
}
__device__ __forceinline__ void upk2(u64 v, float& lo, float& hi) {
    asm("mov.b64 {%0, %1}, %2;" : "=f"(lo), "=f"(hi) : "l"(v));
}
__device__ __forceinline__ u64 fma2(u64 a, u64 b, u64 c) {
    u64 r; asm("fma.rn.f32x2 %0, %1, %2, %3;" : "=l"(r) : "l"(a), "l"(b), "l"(c)); return r;
}
__device__ __forceinline__ u64 mul2(u64 a, u64 b) {
    u64 r; asm("mul.rn.f32x2 %0, %1, %2;" : "=l"(r) : "l"(a), "l"(b)); return r;
}
__device__ __forceinline__ float frcp(float x) {
    float r; asm("rcp.approx.f32 %0, %1;" : "=f"(r) : "f"(x)); return r;
}
__device__ __forceinline__ float fsqrt_ap(float x) {
    float r; asm("sqrt.approx.f32 %0, %1;" : "=f"(r) : "f"(x)); return r;
}

__device__ __forceinline__ float det3(
    float a00, float a01, float a02,
    float a10, float a11, float a12,
    float a20, float a21, float a22) {
    return a00 * (a11 * a22 - a12 * a21)
         - a01 * (a10 * a22 - a12 * a20)
         + a02 * (a10 * a21 - a11 * a20);
}

__device__ __forceinline__ void idx3(int k, int& r0, int& r1, int& r2) {
    r0 = (k == 0) ? 1 : 0;
    r1 = (k <= 1) ? 2 : 1;
    r2 = (k <= 2) ? 3 : 2;
}

// Cofactor C_{k,i} of a 4x4 matrix (sign included); k,i compile-time consts.
__device__ __forceinline__ float cof(const float M[4][4], int k, int i) {
    int r0, r1, r2, c0, c1, c2;
    idx3(k, r0, r1, r2);
    idx3(i, c0, c1, c2);
    float d = det3(M[r0][c0], M[r0][c1], M[r0][c2],
                   M[r1][c0], M[r1][c1], M[r1][c2],
                   M[r2][c0], M[r2][c1], M[r2][c2]);
    return (((k + i) & 1) ? -d : d);
}

// Flat smem tile: [hid][g][j][l16] -> ((hid*GRP + g)*NPAIR + j)*16 + l16.
// Per half-warp row of 16 u64 = 128 B = all 32 banks; conflict-free.
__shared__ u64 s_tile[HPB * GRP * NPAIR * 16];

__device__ __forceinline__ u64 xt(const u64* tb, int g, int j) {
    return tb[(g * NPAIR + j) * 16];
}

__global__ void __launch_bounds__(WPB * 32)
ica_kernel(const float* __restrict__ x, float* __restrict__ out) {
    const int lane = threadIdx.x & 31;
    const int half = lane >> 4;          // position index within the warp
    const int l16  = lane & 15;          // lane within the 16-lane half
    const int wib  = threadIdx.x >> 5;   // warp within block
    const int hid  = (wib << 1) + half;  // half-id within block
    const int pos  = (blockIdx.x * WPB + wib) * 2 + half;

    const float* xp = x + (size_t)pos * (GRP * DD);
    u64* tbase = &s_tile[hid * (GRP * NPAIR * 16) + l16];

    // Stage: batch all 32 global LDG.64 into registers, then store to smem.
    // Lane l16 owns pairs {d = 32j + 2*l16, 32j + 2*l16 + 1}; each (g,j)
    // half-warp transaction covers 16 consecutive u64 = 128 B.
    {
        u64 stage[GRP][NPAIR];
        #pragma unroll
        for (int g = 0; g < GRP; g++)
            #pragma unroll
            for (int j = 0; j < NPAIR; j++)
                stage[g][j] = ((const u64*)(xp + g * DD + j * 32))[l16];
        #pragma unroll
        for (int g = 0; g < GRP; g++)
            #pragma unroll
            for (int j = 0; j < NPAIR; j++)
                tbase[(g * NPAIR + j) * 16] = stage[g][j];
    }
    __syncwarp();

    float W[4][4] = {{1.f,0.f,0.f,0.f},{0.f,1.f,0.f,0.f},
                     {0.f,0.f,1.f,0.f},{0.f,0.f,0.f,1.f}};

    const float eps    = 1e-5f;
    const float RSCALE = 256.0f;           // fold 1/D into the mask
    const float RBIAS  = 256.0f * 1e-5f;   // 256 * eps

    #pragma unroll 1
    for (int it = 0; it < NITER; it++) {
        #pragma unroll
        for (int k = 0; k < GRP; k++) {
            u64 wb0 = pk2(W[k][0], W[k][0]);
            u64 wb1 = pk2(W[k][1], W[k][1]);
            u64 wb2 = pk2(W[k][2], W[k][2]);
            u64 wb3 = pk2(W[k][3], W[k][3]);

            // Fused mask + weighted Gram (10 unique symmetric entries).
            u64 p00=0,p01=0,p02=0,p03=0,p11=0,p12=0,p13=0,p22=0,p23=0,p33=0;
            #pragma unroll
            for (int j = 0; j < NPAIR; j++) {
                u64 x0 = xt(tbase, 0, j);
                u64 x1 = xt(tbase, 1, j);
                u64 x2 = xt(tbase, 2, j);
                u64 x3 = xt(tbase, 3, j);
                u64 y2 = mul2(wb0, x0);
                y2 = fma2(wb1, x1, y2);
                y2 = fma2(wb2, x2, y2);
                y2 = fma2(wb3, x3, y2);
                float y0, y1;
                upk2(y2, y0, y1);
                float r0 = fmaf(fabsf(y0), RSCALE, RBIAS);
                float r1 = fmaf(fabsf(y1), RSCALE, RBIAS);
                u64 uu = pk2(frcp(r0), frcp(r1));

                u64 t0 = mul2(uu, x0);
                u64 t1 = mul2(uu, x1);
                u64 t2 = mul2(uu, x2);
                u64 t3 = mul2(uu, x3);
                p00 = fma2(t0, x0, p00);
                p01 = fma2(t0, x1, p01);
                p02 = fma2(t0, x2, p02);
                p03 = fma2(t0, x3, p03);
                p11 = fma2(t1, x1, p11);
                p12 = fma2(t1, x2, p12);
                p13 = fma2(t1, x3, p13);
                p22 = fma2(t2, x2, p22);
                p23 = fma2(t2, x3, p23);
                p33 = fma2(t3, x3, p33);
            }

            // Packed -> scalar horizontal add.
            float ha, hb;
            float s00, s01, s02, s03, s11, s12, s13, s22, s23, s33;
            upk2(p00, ha, hb); s00 = ha + hb;
            upk2(p01, ha, hb); s01 = ha + hb;
            upk2(p02, ha, hb); s02 = ha + hb;
            upk2(p03, ha, hb); s03 = ha + hb;
            upk2(p11, ha, hb); s11 = ha + hb;
            upk2(p12, ha, hb); s12 = ha + hb;
            upk2(p13, ha, hb); s13 = ha + hb;
            upk2(p22, ha, hb); s22 = ha + hb;
            upk2(p23, ha, hb); s23 = ha + hb;
            upk2(p33, ha, hb); s33 = ha + hb;

            // 4-level butterfly; offsets 8,4,2,1 stay within each 16-lane half.
            #pragma unroll
            for (int off = 8; off > 0; off >>= 1) {
                s00 += __shfl_xor_sync(0xffffffffu, s00, off);
                s01 += __shfl_xor_sync(0xffffffffu, s01, off);
                s02 += __shfl_xor_sync(0xffffffffu, s02, off);
                s03 += __shfl_xor_sync(0xffffffffu, s03, off);
                s11 += __shfl_xor_sync(0xffffffffu, s11, off);
                s12 += __shfl_xor_sync(0xffffffffu, s12, off);
                s13 += __shfl_xor_sync(0xffffffffu, s13, off);
                s22 += __shfl_xor_sync(0xffffffffu, s22, off);
                s23 += __shfl_xor_sync(0xffffffffu, s23, off);
                s33 += __shfl_xor_sync(0xffffffffu, s33, off);
            }

            // V (symmetric; already includes the 1/D factor via the mask).
            float V[4][4];
            V[0][0] = s00;
            V[0][1] = V[1][0] = s01;
            V[0][2] = V[2][0] = s02;
            V[0][3] = V[3][0] = s03;
            V[1][1] = s11;
            V[1][2] = V[2][1] = s12;
            V[1][3] = V[3][1] = s13;
            V[2][2] = s22;
            V[2][3] = V[3][2] = s23;
            V[3][3] = s33;

            // M = W @ V with the current (partially updated) W.
            float M[4][4];
            #pragma unroll
            for (int r = 0; r < 4; r++)
                #pragma unroll
                for (int c = 0; c < 4; c++) {
                    float s = W[r][0] * V[0][c];
                    s = fmaf(W[r][1], V[1][c], s);
                    s = fmaf(W[r][2], V[2][c], s);
                    s = fmaf(W[r][3], V[3][c], s);
                    M[r][c] = s;
                }

            // Row-k cofactors: solution of M w = e_k is c/det.
            float c0 = cof(M, k, 0);
            float c1 = cof(M, k, 1);
            float c2 = cof(M, k, 2);
            float c3 = cof(M, k, 3);
            float det = M[k][0]*c0 + M[k][1]*c1 + M[k][2]*c2 + M[k][3]*c3;

            // w/(sqrt(w'Vw)+eps) is scale-invariant up to sign:
            // W[k] = c * copysign(1/(sqrt(c'Vc) + eps*|det|), det).
            float t0 = V[0][0]*c0 + V[0][1]*c1 + V[0][2]*c2 + V[0][3]*c3;
            float t1 = V[1][0]*c0 + V[1][1]*c1 + V[1][2]*c2 + V[1][3]*c3;
            float t2 = V[2][0]*c0 + V[2][1]*c1 + V[2][2]*c2 + V[2][3]*c3;
            float t3 = V[3][0]*c0 + V[3][1]*c1 + V[3][2]*c2 + V[3][3]*c3;
            float s  = c0*t0 + c1*t1 + c2*t2 + c3*t3;
            float denom = fmaf(eps, fabsf(det), fsqrt_ap(s));
            float inv = copysignf(frcp(denom), det);
            W[k][0] = c0 * inv;
            W[k][1] = c1 * inv;
            W[k][2] = c2 * inv;
            W[k][3] = c3 * inv;
        }
    }

    // scale_g = diag(inv(W))_g = C_{g,g}(W) / det(W); premultiply into rows.
    float d0 = cof(W, 0, 0);
    float d1 = cof(W, 0, 1);
    float d2 = cof(W, 0, 2);
    float d3 = cof(W, 0, 3);
    float detW = W[0][0]*d0 + W[0][1]*d1 + W[0][2]*d2 + W[0][3]*d3;
    float idetW = frcp(detW);
    float scale[4];
    scale[0] = d0 * idetW;
    scale[1] = cof(W, 1, 1) * idetW;
    scale[2] = cof(W, 2, 2) * idetW;
    scale[3] = cof(W, 3, 3) * idetW;

    float* op = out + (size_t)pos * (GRP * DD);
    #pragma unroll
    for (int g = 0; g < GRP; g++) {
        // Fold the output scale into the broadcast row (saves a mul2 per j).
        float a0 = W[g][0] * scale[g];
        float a1 = W[g][1] * scale[g];
        float a2 = W[g][2] * scale[g];
        float a3 = W[g][3] * scale[g];
        u64 wb0 = pk2(a0, a0);
        u64 wb1 = pk2(a1, a1);
        u64 wb2 = pk2(a2, a2);
        u64 wb3 = pk2(a3, a3);
        #pragma unroll
        for (int j = 0; j < NPAIR; j++) {
            u64 y2 = mul2(wb0, xt(tbase, 0, j));
            y2 = fma2(wb1, xt(tbase, 1, j), y2);
            y2 = fma2(wb2, xt(tbase, 2, j), y2);
            y2 = fma2(wb3, xt(tbase, 3, j), y2);
            ((u64*)(op + g * DD + j * 32))[l16] = y2;
        }
    }
}

extern "C" void kernel_launch(void* const* d_in, const int* in_sizes, int n_in,
                              void* d_out, int out_size) {
    const float* x = (const float*)d_in[0];
    float* out = (float*)d_out;
    (void)in_sizes; (void)n_in; (void)out_size;
    // 8192 positions, 2 per warp, WPB warps per block.
    ica_kernel<<<NPOS / HPB, WPB * 32>>>(x, out);
}